// round 8
// baseline (speedup 1.0000x reference)
#include <cuda_runtime.h>
#include <math.h>
#include <stdint.h>

// Problem constants
constexpr int S_LEN = 4096;
constexpr int BATCH = 2;
constexpr int EMB   = 512;   // E and also H*D
constexpr int NH    = 8;
constexpr int DH    = 64;
constexpr int HALF  = 256;   // sliding window half-width
constexpr int ROWS  = BATCH * S_LEN;  // 8192

// Scratch (allocation-free rule: __device__ globals)
__device__ float g_q[(size_t)ROWS * EMB];
__device__ float g_k[(size_t)ROWS * EMB];
__device__ float g_v[(size_t)ROWS * EMB];
__device__ float g_att[(size_t)ROWS * EMB];

// ---------------------------------------------------------------------------
// bf16 split helpers
// ---------------------------------------------------------------------------
__device__ __forceinline__ void split2(float x0, float x1,
                                       uint32_t& hp, uint32_t& lp) {
    asm("cvt.rn.bf16x2.f32 %0, %1, %2;" : "=r"(hp) : "f"(x1), "f"(x0));
    float h0 = __uint_as_float(hp << 16);
    float h1 = __uint_as_float(hp & 0xffff0000u);
    float r0 = x0 - h0;
    float r1 = x1 - h1;
    asm("cvt.rn.bf16x2.f32 %0, %1, %2;" : "=r"(lp) : "f"(r1), "f"(r0));
}

__device__ __forceinline__ void mma_bf16(float d[4], const uint32_t a[4],
                                         const uint32_t b[2]) {
    asm volatile(
        "mma.sync.aligned.m16n8k16.row.col.f32.bf16.bf16.f32 "
        "{%0,%1,%2,%3}, {%4,%5,%6,%7}, {%8,%9}, {%0,%1,%2,%3};\n"
        : "+f"(d[0]), "+f"(d[1]), "+f"(d[2]), "+f"(d[3])
        : "r"(a[0]), "r"(a[1]), "r"(a[2]), "r"(a[3]), "r"(b[0]), "r"(b[1]));
}

__device__ __forceinline__ void ldsm_x4(uint32_t r[4], uint32_t addr) {
    asm volatile(
        "ldmatrix.sync.aligned.m8n8.x4.shared.b16 {%0,%1,%2,%3}, [%4];"
        : "=r"(r[0]), "=r"(r[1]), "=r"(r[2]), "=r"(r[3]) : "r"(addr));
}

__device__ __forceinline__ uint32_t smem_u32(const void* p) {
    return (uint32_t)__cvta_generic_to_shared(p);
}

// ---------------------------------------------------------------------------
// Split-bf16 tensor-core GEMM (validated in R4). C[M,N] = A[M,K] @ B[K,N].
// ---------------------------------------------------------------------------
constexpr int GBM = 128, GBN = 128, GBK = 32;
constexpr int KP  = GBK / 2;
constexpr int ASTR = 20;
constexpr int BSTR = 136;
constexpr int A_STAGE = GBM * ASTR;
constexpr int B_STAGE = KP * BSTR;
constexpr int GEMM_SMEM_BYTES = (4 * A_STAGE + 4 * B_STAGE) * 4;

__global__ __launch_bounds__(256, 1) void gemm_bf16_kernel(
    const float* __restrict__ A, const float* __restrict__ B,
    float* __restrict__ C, int M, int N, int K)
{
    extern __shared__ uint32_t sm[];
    uint32_t* sAh = sm;
    uint32_t* sAl = sAh + 2 * A_STAGE;
    uint32_t* sBh = sAl + 2 * A_STAGE;
    uint32_t* sBl = sBh + 2 * B_STAGE;

    const int tid  = threadIdx.x;
    const int lane = tid & 31;
    const int wid  = tid >> 5;
    const int m_base = (wid >> 2) * 64;
    const int n_base = (wid & 3) * 32;
    const int row0 = blockIdx.y * GBM;
    const int col0 = blockIdx.x * GBN;

    const int arow  = tid >> 2;
    const int acolg = (tid & 3) * 8;
    const int akp   = (tid & 3) * 4;
    const int brow = tid >> 5;
    const int bcol = (tid & 31) * 4;

    const float* pA0 = A + (size_t)(row0 + arow) * K + acolg;
    const float* pA1 = A + (size_t)(row0 + arow + 64) * K + acolg;
    const float* pB00 = B + (size_t)(2 * brow) * N + col0 + bcol;
    const float* pB01 = B + (size_t)(2 * brow + 1) * N + col0 + bcol;
    const float* pB10 = B + (size_t)(2 * (brow + 8)) * N + col0 + bcol;
    const float* pB11 = B + (size_t)(2 * (brow + 8) + 1) * N + col0 + bcol;

    const int NT = K / GBK;

    float acc[4][4][4] = {};
    float4 fa00, fa01, fa10, fa11;
    float4 fb00, fb01, fb10, fb11;

    #define STORE_A(dsth, dstl, r, v0, v1)                                    \
        {                                                                     \
            uint32_t h0, l0, h1, l1, h2, l2, h3, l3;                          \
            split2((v0).x, (v0).y, h0, l0);                                   \
            split2((v0).z, (v0).w, h1, l1);                                   \
            split2((v1).x, (v1).y, h2, l2);                                   \
            split2((v1).z, (v1).w, h3, l3);                                   \
            *(uint4*)&(dsth)[(r) * ASTR + akp] = make_uint4(h0, h1, h2, h3);  \
            *(uint4*)&(dstl)[(r) * ASTR + akp] = make_uint4(l0, l1, l2, l3);  \
        }

    #define STORE_B(dsth, dstl, kp, v0, v1)                                   \
        {                                                                     \
            uint32_t h0, l0, h1, l1, h2, l2, h3, l3;                          \
            split2((v0).x, (v1).x, h0, l0);                                   \
            split2((v0).y, (v1).y, h1, l1);                                   \
            split2((v0).z, (v1).z, h2, l2);                                   \
            split2((v0).w, (v1).w, h3, l3);                                   \
            *(uint4*)&(dsth)[(kp) * BSTR + bcol] = make_uint4(h0, h1, h2, h3);\
            *(uint4*)&(dstl)[(kp) * BSTR + bcol] = make_uint4(l0, l1, l2, l3);\
        }

    fa00 = *(const float4*)(pA0);
    fa01 = *(const float4*)(pA0 + 4);
    fa10 = *(const float4*)(pA1);
    fa11 = *(const float4*)(pA1 + 4);
    fb00 = *(const float4*)(pB00);
    fb01 = *(const float4*)(pB01);
    fb10 = *(const float4*)(pB10);
    fb11 = *(const float4*)(pB11);

    STORE_A(sAh, sAl, arow, fa00, fa01);
    STORE_A(sAh, sAl, arow + 64, fa10, fa11);
    STORE_B(sBh, sBl, brow, fb00, fb01);
    STORE_B(sBh, sBl, brow + 8, fb10, fb11);
    __syncthreads();

    const int gr = lane >> 2;
    const int qc = lane & 3;

    for (int kt = 0; kt < NT; kt++) {
        if (kt + 1 < NT) {
            int ko = (kt + 1) * GBK;
            fa00 = *(const float4*)(pA0 + ko);
            fa01 = *(const float4*)(pA0 + ko + 4);
            fa10 = *(const float4*)(pA1 + ko);
            fa11 = *(const float4*)(pA1 + ko + 4);
            fb00 = *(const float4*)(pB00 + (size_t)ko * N);
            fb01 = *(const float4*)(pB01 + (size_t)ko * N);
            fb10 = *(const float4*)(pB10 + (size_t)ko * N);
            fb11 = *(const float4*)(pB11 + (size_t)ko * N);
        }

        const uint32_t* Ah = sAh + (kt & 1) * A_STAGE;
        const uint32_t* Al = sAl + (kt & 1) * A_STAGE;
        const uint32_t* Bh = sBh + (kt & 1) * B_STAGE;
        const uint32_t* Bl = sBl + (kt & 1) * B_STAGE;

        #pragma unroll
        for (int ks = 0; ks < 2; ks++) {
            const int kp0 = ks * 8 + qc;
            uint32_t ah[4][4], al[4][4], bh[4][2], bl[4][2];
            #pragma unroll
            for (int mt = 0; mt < 4; mt++) {
                const int m = m_base + mt * 16 + gr;
                ah[mt][0] = Ah[m * ASTR + kp0];
                ah[mt][1] = Ah[(m + 8) * ASTR + kp0];
                ah[mt][2] = Ah[m * ASTR + kp0 + 4];
                ah[mt][3] = Ah[(m + 8) * ASTR + kp0 + 4];
                al[mt][0] = Al[m * ASTR + kp0];
                al[mt][1] = Al[(m + 8) * ASTR + kp0];
                al[mt][2] = Al[m * ASTR + kp0 + 4];
                al[mt][3] = Al[(m + 8) * ASTR + kp0 + 4];
            }
            #pragma unroll
            for (int nt = 0; nt < 4; nt++) {
                const int n = n_base + nt * 8 + gr;
                bh[nt][0] = Bh[kp0 * BSTR + n];
                bh[nt][1] = Bh[(kp0 + 4) * BSTR + n];
                bl[nt][0] = Bl[kp0 * BSTR + n];
                bl[nt][1] = Bl[(kp0 + 4) * BSTR + n];
            }
            #pragma unroll
            for (int mt = 0; mt < 4; mt++)
                #pragma unroll
                for (int nt = 0; nt < 4; nt++) {
                    mma_bf16(acc[mt][nt], ah[mt], bh[nt]);
                    mma_bf16(acc[mt][nt], ah[mt], bl[nt]);
                    mma_bf16(acc[mt][nt], al[mt], bh[nt]);
                }
        }

        if (kt + 1 < NT) {
            uint32_t* dAh = sAh + ((kt + 1) & 1) * A_STAGE;
            uint32_t* dAl = sAl + ((kt + 1) & 1) * A_STAGE;
            uint32_t* dBh = sBh + ((kt + 1) & 1) * B_STAGE;
            uint32_t* dBl = sBl + ((kt + 1) & 1) * B_STAGE;
            STORE_A(dAh, dAl, arow, fa00, fa01);
            STORE_A(dAh, dAl, arow + 64, fa10, fa11);
            STORE_B(dBh, dBl, brow, fb00, fb01);
            STORE_B(dBh, dBl, brow + 8, fb10, fb11);
        }
        __syncthreads();
    }
    #undef STORE_A
    #undef STORE_B

    #pragma unroll
    for (int mt = 0; mt < 4; mt++) {
        #pragma unroll
        for (int nt = 0; nt < 4; nt++) {
            int r = row0 + m_base + mt * 16 + gr;
            int c = col0 + n_base + nt * 8 + 2 * qc;
            *(float2*)&C[(size_t)r * N + c] =
                make_float2(acc[mt][nt][0], acc[mt][nt][1]);
            *(float2*)&C[(size_t)(r + 8) * N + c] =
                make_float2(acc[mt][nt][2], acc[mt][nt][3]);
        }
    }
}

// ---------------------------------------------------------------------------
// Tensor-core windowed flash attention, bf16 hi/lo split, ldmatrix fragments.
// CTA = (b, h, 64-query tile), 512 threads (16 warps: QK 4x4, PV 4x4).
// Layouts (u32 words, all rows 16B-aligned, odd quad strides => LDSM
// conflict-free):
//   sQ [q=64][kp]   stride 36
//   sK [key=192][kp] stride 36
//   sV [d=64][keypair] stride 100  (V transposed)
//   sP [q=64][keypair] stride 100
// ---------------------------------------------------------------------------
constexpr int AQT = 64;
constexpr int AKT = 192;
constexpr int QSTR2 = 36;
constexpr int KSTR2 = 36;
constexpr int VSTR2 = 100;
constexpr int PSTR2 = 100;
constexpr int ATHREADS = 512;

constexpr int OFF_QH = 0;
constexpr int OFF_QL = OFF_QH + AQT * QSTR2;        // 2304
constexpr int OFF_KH = OFF_QL + AQT * QSTR2;        // 4608
constexpr int OFF_KL = OFF_KH + AKT * KSTR2;        // 11520
constexpr int OFF_VH = OFF_KL + AKT * KSTR2;        // 18432
constexpr int OFF_VL = OFF_VH + 64 * VSTR2;         // 24832
constexpr int OFF_PH = OFF_VL + 64 * VSTR2;         // 31232
constexpr int OFF_PL = OFF_PH + AQT * PSTR2;        // 37632
constexpr int OFF_RED = OFF_PL + AQT * PSTR2;       // 44032
constexpr int OFF_M  = OFF_RED + 256;
constexpr int OFF_L  = OFF_M + 64;
constexpr int OFF_F  = OFF_L + 64;
constexpr int ATTN_SMEM_WORDS = OFF_F + 64;         // 44480
constexpr int ATTN_SMEM_BYTES = ATTN_SMEM_WORDS * 4;  // 177920

__global__ __launch_bounds__(ATHREADS, 1) void attn_tc_kernel()
{
    extern __shared__ uint32_t sm[];
    uint32_t* sQh = sm + OFF_QH;
    uint32_t* sQl = sm + OFF_QL;
    uint32_t* sKh = sm + OFF_KH;
    uint32_t* sKl = sm + OFF_KL;
    uint32_t* sVh = sm + OFF_VH;
    uint32_t* sVl = sm + OFF_VL;
    uint32_t* sPh = sm + OFF_PH;
    uint32_t* sPl = sm + OFF_PL;
    float* red = (float*)(sm + OFF_RED);
    float* mS  = (float*)(sm + OFF_M);
    float* lS  = (float*)(sm + OFF_L);
    float* fS  = (float*)(sm + OFF_F);

    const int tid  = threadIdx.x;
    const int lane = tid & 31;
    const int wid  = tid >> 5;     // 0..15
    const int gr = lane >> 2;
    const int qc = lane & 3;
    const int wm = wid >> 2;       // 0..3
    const int wn = wid & 3;        // 0..3
    const int m0 = wm * 16;

    const int t0 = blockIdx.x * AQT;
    const int h  = blockIdx.y;
    const int b  = blockIdx.z;
    const float slope = exp2f(-(float)(h + 1));

    const float* Qb = g_q   + (size_t)b * S_LEN * EMB + h * DH;
    const float* Kb = g_k   + (size_t)b * S_LEN * EMB + h * DH;
    const float* Vb = g_v   + (size_t)b * S_LEN * EMB + h * DH;
    float*       Ob = g_att + (size_t)b * S_LEN * EMB + h * DH;

    // ldmatrix lane-address components (elements; *4 for bytes)
    const int lrow8  = (lane & 7);
    const int lmsel  = (lane >> 3) & 1;   // a-frag: +8 rows; b-frag: +4 kp
    const int lhsel  = (lane >> 4) & 1;   // a-frag: +4 kp;  b-frag: +8 rows

    // A-fragment (Q or P): row = base + lrow8 + lmsel*8, col = lhsel*4
    const uint32_t qh_base = smem_u32(sQh) +
        (((m0 + lrow8 + lmsel * 8) * QSTR2) + lhsel * 4) * 4;
    const uint32_t ql_base = qh_base + (OFF_QL - OFF_QH) * 4;
    const uint32_t ph_base = smem_u32(sPh) +
        (((m0 + lrow8 + lmsel * 8) * PSTR2) + lhsel * 4) * 4;
    const uint32_t pl_base = ph_base + (OFF_PL - OFF_PH) * 4;
    // B-fragment (K): row = nbase + lrow8 + lhsel*8, col = lmsel*4
    const int nbase = wn * 48;
    const uint32_t kh_base = smem_u32(sKh) +
        (((nbase + lrow8 + lhsel * 8) * KSTR2) + lmsel * 4) * 4;
    const uint32_t kl_base = kh_base + (OFF_KL - OFF_KH) * 4;
    // B-fragment (V): row = nb2 + lrow8 + lhsel*8, col = lmsel*4
    const int nb2 = wn * 16;
    const uint32_t vh_base = smem_u32(sVh) +
        (((nb2 + lrow8 + lhsel * 8) * VSTR2) + lmsel * 4) * 4;
    const uint32_t vl_base = vh_base + (OFF_VL - OFF_VH) * 4;

    // Load Q tile: row q holds kp 0..31
    for (int idx = tid; idx < AQT * 16; idx += ATHREADS) {
        int q = idx >> 4;
        int dg = idx & 15;
        float4 v = *(const float4*)&Qb[(size_t)(t0 + q) * EMB + dg * 4];
        uint32_t h0, l0, h1, l1;
        split2(v.x, v.y, h0, l0);
        split2(v.z, v.w, h1, l1);
        int o = q * QSTR2 + 2 * dg;
        sQh[o] = h0; sQh[o + 1] = h1;
        sQl[o] = l0; sQl[o + 1] = l1;
    }
    if (tid < AQT) { mS[tid] = -1e30f; lS[tid] = 0.0f; }

    float o[2][4] = {};

    const int base = t0 - HALF;

    #pragma unroll 1
    for (int c = 0; c < 3; c++) {
        const int cs = base + c * AKT;
        if (cs + AKT <= 0 || cs >= S_LEN) continue;

        // ---- load K chunk: row key holds kp 0..31 ----
        for (int idx = tid; idx < AKT * 16; idx += ATHREADS) {
            int key = idx >> 4;
            int dg = idx & 15;
            int T = cs + key;
            float4 kv = make_float4(0.f, 0.f, 0.f, 0.f);
            if (T >= 0 && T < S_LEN)
                kv = *(const float4*)&Kb[(size_t)T * EMB + dg * 4];
            uint32_t h0, l0, h1, l1;
            split2(kv.x, kv.y, h0, l0);
            split2(kv.z, kv.w, h1, l1);
            int oo = key * KSTR2 + 2 * dg;
            sKh[oo] = h0; sKh[oo + 1] = h1;
            sKl[oo] = l0; sKl[oo + 1] = l1;
        }
        // ---- load V transposed: row d holds keypairs 0..95 ----
        for (int idx = tid; idx < 96 * 16; idx += ATHREADS) {
            int kp = idx >> 4;
            int dg = idx & 15;
            int d = dg * 4;
            int T0 = cs + 2 * kp, T1 = T0 + 1;
            float4 v0 = make_float4(0.f, 0.f, 0.f, 0.f);
            float4 v1 = make_float4(0.f, 0.f, 0.f, 0.f);
            if (T0 >= 0 && T0 < S_LEN) v0 = *(const float4*)&Vb[(size_t)T0 * EMB + d];
            if (T1 >= 0 && T1 < S_LEN) v1 = *(const float4*)&Vb[(size_t)T1 * EMB + d];
            uint32_t hp, lp;
            split2(v0.x, v1.x, hp, lp); sVh[(d + 0) * VSTR2 + kp] = hp; sVl[(d + 0) * VSTR2 + kp] = lp;
            split2(v0.y, v1.y, hp, lp); sVh[(d + 1) * VSTR2 + kp] = hp; sVl[(d + 1) * VSTR2 + kp] = lp;
            split2(v0.z, v1.z, hp, lp); sVh[(d + 2) * VSTR2 + kp] = hp; sVl[(d + 2) * VSTR2 + kp] = lp;
            split2(v0.w, v1.w, hp, lp); sVh[(d + 3) * VSTR2 + kp] = hp; sVl[(d + 3) * VSTR2 + kp] = lp;
        }
        __syncthreads();

        // ---- S = Q @ K^T : warp tile 16 x 48 ----
        float s[6][4];
        #pragma unroll
        for (int nt = 0; nt < 6; nt++)
            #pragma unroll
            for (int i = 0; i < 4; i++) s[nt][i] = 0.f;

        #pragma unroll
        for (int ks = 0; ks < 4; ks++) {
            uint32_t ah[4], al[4];
            ldsm_x4(ah, qh_base + ks * 32);
            ldsm_x4(al, ql_base + ks * 32);
            #pragma unroll
            for (int ntp = 0; ntp < 3; ntp++) {
                uint32_t bh[4], bl[4];
                ldsm_x4(bh, kh_base + ks * 32 + ntp * (16 * KSTR2 * 4));
                ldsm_x4(bl, kl_base + ks * 32 + ntp * (16 * KSTR2 * 4));
                mma_bf16(s[2 * ntp],     ah, bh);
                mma_bf16(s[2 * ntp],     ah, bl);
                mma_bf16(s[2 * ntp],     al, bh);
                mma_bf16(s[2 * ntp + 1], ah, bh + 2);
                mma_bf16(s[2 * ntp + 1], ah, bl + 2);
                mma_bf16(s[2 * ntp + 1], al, bh + 2);
            }
        }

        // ---- scale + ALiBi + window mask; per-row max ----
        const int trow0 = t0 + m0 + gr;
        const int trow1 = trow0 + 8;
        float mx0 = -1e30f, mx1 = -1e30f;
        #pragma unroll
        for (int nt = 0; nt < 6; nt++) {
            int T0 = cs + nbase + nt * 8 + 2 * qc;
            int T1 = T0 + 1;
            bool in0 = (T0 >= 0) && (T0 < S_LEN);
            bool in1 = (T1 >= 0) && (T1 < S_LEN);
            int a00 = abs(trow0 - T0), a01 = abs(trow0 - T1);
            int a10 = abs(trow1 - T0), a11 = abs(trow1 - T1);
            s[nt][0] = (in0 && a00 <= HALF) ? fmaf(s[nt][0], 0.125f, -slope * (float)a00) : -1e30f;
            s[nt][1] = (in1 && a01 <= HALF) ? fmaf(s[nt][1], 0.125f, -slope * (float)a01) : -1e30f;
            s[nt][2] = (in0 && a10 <= HALF) ? fmaf(s[nt][2], 0.125f, -slope * (float)a10) : -1e30f;
            s[nt][3] = (in1 && a11 <= HALF) ? fmaf(s[nt][3], 0.125f, -slope * (float)a11) : -1e30f;
            mx0 = fmaxf(mx0, fmaxf(s[nt][0], s[nt][1]));
            mx1 = fmaxf(mx1, fmaxf(s[nt][2], s[nt][3]));
        }
        mx0 = fmaxf(mx0, __shfl_xor_sync(0xffffffffu, mx0, 1));
        mx0 = fmaxf(mx0, __shfl_xor_sync(0xffffffffu, mx0, 2));
        mx1 = fmaxf(mx1, __shfl_xor_sync(0xffffffffu, mx1, 1));
        mx1 = fmaxf(mx1, __shfl_xor_sync(0xffffffffu, mx1, 2));
        if (qc == 0) {
            red[(m0 + gr) * 4 + wn] = mx0;
            red[(m0 + gr + 8) * 4 + wn] = mx1;
        }
        __syncthreads();

        if (tid < AQT) {
            float cm = fmaxf(fmaxf(red[tid * 4], red[tid * 4 + 1]),
                             fmaxf(red[tid * 4 + 2], red[tid * 4 + 3]));
            float mold = mS[tid];
            float mnew = fmaxf(mold, cm);
            fS[tid] = __expf(mold - mnew);
            mS[tid] = mnew;
        }
        __syncthreads();

        // ---- exp, stage P [q][kp], partial sums, rescale O ----
        const float mrow0 = mS[m0 + gr];
        const float mrow1 = mS[m0 + gr + 8];
        float sum0 = 0.f, sum1 = 0.f;
        #pragma unroll
        for (int nt = 0; nt < 6; nt++) {
            float p00 = (s[nt][0] > -5e29f) ? __expf(s[nt][0] - mrow0) : 0.f;
            float p01 = (s[nt][1] > -5e29f) ? __expf(s[nt][1] - mrow0) : 0.f;
            float p10 = (s[nt][2] > -5e29f) ? __expf(s[nt][2] - mrow1) : 0.f;
            float p11 = (s[nt][3] > -5e29f) ? __expf(s[nt][3] - mrow1) : 0.f;
            sum0 += p00 + p01;
            sum1 += p10 + p11;
            int kp = wn * 24 + nt * 4 + qc;
            uint32_t hp, lp;
            split2(p00, p01, hp, lp);
            sPh[(m0 + gr) * PSTR2 + kp] = hp;
            sPl[(m0 + gr) * PSTR2 + kp] = lp;
            split2(p10, p11, hp, lp);
            sPh[(m0 + gr + 8) * PSTR2 + kp] = hp;
            sPl[(m0 + gr + 8) * PSTR2 + kp] = lp;
        }
        sum0 += __shfl_xor_sync(0xffffffffu, sum0, 1);
        sum0 += __shfl_xor_sync(0xffffffffu, sum0, 2);
        sum1 += __shfl_xor_sync(0xffffffffu, sum1, 1);
        sum1 += __shfl_xor_sync(0xffffffffu, sum1, 2);
        if (qc == 0) {
            red[(m0 + gr) * 4 + wn] = sum0;
            red[(m0 + gr + 8) * 4 + wn] = sum1;
        }
        const float f0 = fS[m0 + gr];
        const float f1 = fS[m0 + gr + 8];
        #pragma unroll
        for (int nt = 0; nt < 2; nt++) {
            o[nt][0] *= f0; o[nt][1] *= f0;
            o[nt][2] *= f1; o[nt][3] *= f1;
        }
        __syncthreads();

        if (tid < AQT)
            lS[tid] = lS[tid] * fS[tid] + red[tid * 4] + red[tid * 4 + 1]
                      + red[tid * 4 + 2] + red[tid * 4 + 3];

        // ---- O += P @ V : warp tile 16 x 16 ----
        #pragma unroll
        for (int ks = 0; ks < 12; ks++) {
            uint32_t ah[4], al[4], bh[4], bl[4];
            ldsm_x4(ah, ph_base + ks * 32);
            ldsm_x4(al, pl_base + ks * 32);
            ldsm_x4(bh, vh_base + ks * 32);
            ldsm_x4(bl, vl_base + ks * 32);
            mma_bf16(o[0], ah, bh);
            mma_bf16(o[0], ah, bl);
            mma_bf16(o[0], al, bh);
            mma_bf16(o[1], ah, bh + 2);
            mma_bf16(o[1], ah, bl + 2);
            mma_bf16(o[1], al, bh + 2);
        }
        __syncthreads();
    }

    // ---- normalize and write ----
    const int trow0 = t0 + m0 + gr;
    const float inv0 = 1.0f / lS[m0 + gr];
    const float inv1 = 1.0f / lS[m0 + gr + 8];
    #pragma unroll
    for (int nt = 0; nt < 2; nt++) {
        int d = wn * 16 + nt * 8 + 2 * qc;
        *(float2*)&Ob[(size_t)trow0 * EMB + d] =
            make_float2(o[nt][0] * inv0, o[nt][1] * inv0);
        *(float2*)&Ob[(size_t)(trow0 + 8) * EMB + d] =
            make_float2(o[nt][2] * inv1, o[nt][3] * inv1);
    }
}

// ---------------------------------------------------------------------------
extern "C" void kernel_launch(void* const* d_in, const int* in_sizes, int n_in,
                              void* d_out, int out_size)
{
    (void)in_sizes; (void)n_in; (void)out_size;
    const float* inputs_q  = (const float*)d_in[0];
    const float* inputs_kv = (const float*)d_in[1];
    const float* w_q = (const float*)d_in[2];
    const float* w_k = (const float*)d_in[3];
    const float* w_v = (const float*)d_in[4];
    const float* w_o = (const float*)d_in[5];
    float* out = (float*)d_out;

    float *qb, *kb, *vb, *ab;
    cudaGetSymbolAddress((void**)&qb, g_q);
    cudaGetSymbolAddress((void**)&kb, g_k);
    cudaGetSymbolAddress((void**)&vb, g_v);
    cudaGetSymbolAddress((void**)&ab, g_att);

    cudaFuncSetAttribute(gemm_bf16_kernel,
                         cudaFuncAttributeMaxDynamicSharedMemorySize,
                         GEMM_SMEM_BYTES);
    cudaFuncSetAttribute(attn_tc_kernel,
                         cudaFuncAttributeMaxDynamicSharedMemorySize,
                         ATTN_SMEM_BYTES);

    dim3 gGemm(EMB / GBN, ROWS / GBM);   // (4, 64)
    gemm_bf16_kernel<<<gGemm, 256, GEMM_SMEM_BYTES>>>(inputs_q,  w_q, qb, ROWS, EMB, EMB);
    gemm_bf16_kernel<<<gGemm, 256, GEMM_SMEM_BYTES>>>(inputs_kv, w_k, kb, ROWS, EMB, EMB);
    gemm_bf16_kernel<<<gGemm, 256, GEMM_SMEM_BYTES>>>(inputs_kv, w_v, vb, ROWS, EMB, EMB);

    dim3 gAttn(S_LEN / AQT, NH, BATCH);  // (64, 8, 2)
    attn_tc_kernel<<<gAttn, ATHREADS, ATTN_SMEM_BYTES>>>();

    gemm_bf16_kernel<<<gGemm, 256, GEMM_SMEM_BYTES>>>(ab, w_o, out, ROWS, EMB, EMB);
}

// round 10
// speedup vs baseline: 1.0484x; 1.0484x over previous
#include <cuda_runtime.h>
#include <math.h>
#include <stdint.h>

// Problem constants
constexpr int S_LEN = 4096;
constexpr int BATCH = 2;
constexpr int EMB   = 512;   // E and also H*D
constexpr int NH    = 8;
constexpr int DH    = 64;
constexpr int HALF  = 256;   // sliding window half-width
constexpr int ROWS  = BATCH * S_LEN;  // 8192

// Scratch (allocation-free rule: __device__ globals)
__device__ float g_q[(size_t)ROWS * EMB];
__device__ float g_k[(size_t)ROWS * EMB];
__device__ float g_v[(size_t)ROWS * EMB];
__device__ float g_att[(size_t)ROWS * EMB];

// ---------------------------------------------------------------------------
// bf16 split helpers
// ---------------------------------------------------------------------------
__device__ __forceinline__ void split2(float x0, float x1,
                                       uint32_t& hp, uint32_t& lp) {
    asm("cvt.rn.bf16x2.f32 %0, %1, %2;" : "=r"(hp) : "f"(x1), "f"(x0));
    float h0 = __uint_as_float(hp << 16);
    float h1 = __uint_as_float(hp & 0xffff0000u);
    float r0 = x0 - h0;
    float r1 = x1 - h1;
    asm("cvt.rn.bf16x2.f32 %0, %1, %2;" : "=r"(lp) : "f"(r1), "f"(r0));
}

__device__ __forceinline__ void mma_bf16(float d[4], const uint32_t a[4],
                                         const uint32_t b[2]) {
    asm volatile(
        "mma.sync.aligned.m16n8k16.row.col.f32.bf16.bf16.f32 "
        "{%0,%1,%2,%3}, {%4,%5,%6,%7}, {%8,%9}, {%0,%1,%2,%3};\n"
        : "+f"(d[0]), "+f"(d[1]), "+f"(d[2]), "+f"(d[3])
        : "r"(a[0]), "r"(a[1]), "r"(a[2]), "r"(a[3]), "r"(b[0]), "r"(b[1]));
}

__device__ __forceinline__ void ldsm_x4(uint32_t r[4], uint32_t addr) {
    asm volatile(
        "ldmatrix.sync.aligned.m8n8.x4.shared.b16 {%0,%1,%2,%3}, [%4];"
        : "=r"(r[0]), "=r"(r[1]), "=r"(r[2]), "=r"(r[3]) : "r"(addr));
}

__device__ __forceinline__ uint32_t smem_u32(const void* p) {
    return (uint32_t)__cvta_generic_to_shared(p);
}

// ---------------------------------------------------------------------------
// Split-bf16 tensor-core GEMM (validated in R4). C[M,N] = A[M,K] @ B[K,N].
// ---------------------------------------------------------------------------
constexpr int GBM = 128, GBN = 128, GBK = 32;
constexpr int KP  = GBK / 2;
constexpr int ASTR = 20;
constexpr int BSTR = 136;
constexpr int A_STAGE = GBM * ASTR;
constexpr int B_STAGE = KP * BSTR;
constexpr int GEMM_SMEM_BYTES = (4 * A_STAGE + 4 * B_STAGE) * 4;

__global__ __launch_bounds__(256, 1) void gemm_bf16_kernel(
    const float* __restrict__ A, const float* __restrict__ B,
    float* __restrict__ C, int M, int N, int K)
{
    extern __shared__ uint32_t sm[];
    uint32_t* sAh = sm;
    uint32_t* sAl = sAh + 2 * A_STAGE;
    uint32_t* sBh = sAl + 2 * A_STAGE;
    uint32_t* sBl = sBh + 2 * B_STAGE;

    const int tid  = threadIdx.x;
    const int lane = tid & 31;
    const int wid  = tid >> 5;
    const int m_base = (wid >> 2) * 64;
    const int n_base = (wid & 3) * 32;
    const int row0 = blockIdx.y * GBM;
    const int col0 = blockIdx.x * GBN;

    const int arow  = tid >> 2;
    const int acolg = (tid & 3) * 8;
    const int akp   = (tid & 3) * 4;
    const int brow = tid >> 5;
    const int bcol = (tid & 31) * 4;

    const float* pA0 = A + (size_t)(row0 + arow) * K + acolg;
    const float* pA1 = A + (size_t)(row0 + arow + 64) * K + acolg;
    const float* pB00 = B + (size_t)(2 * brow) * N + col0 + bcol;
    const float* pB01 = B + (size_t)(2 * brow + 1) * N + col0 + bcol;
    const float* pB10 = B + (size_t)(2 * (brow + 8)) * N + col0 + bcol;
    const float* pB11 = B + (size_t)(2 * (brow + 8) + 1) * N + col0 + bcol;

    const int NT = K / GBK;

    float acc[4][4][4] = {};
    float4 fa00, fa01, fa10, fa11;
    float4 fb00, fb01, fb10, fb11;

    #define STORE_A(dsth, dstl, r, v0, v1)                                    \
        {                                                                     \
            uint32_t h0, l0, h1, l1, h2, l2, h3, l3;                          \
            split2((v0).x, (v0).y, h0, l0);                                   \
            split2((v0).z, (v0).w, h1, l1);                                   \
            split2((v1).x, (v1).y, h2, l2);                                   \
            split2((v1).z, (v1).w, h3, l3);                                   \
            *(uint4*)&(dsth)[(r) * ASTR + akp] = make_uint4(h0, h1, h2, h3);  \
            *(uint4*)&(dstl)[(r) * ASTR + akp] = make_uint4(l0, l1, l2, l3);  \
        }

    #define STORE_B(dsth, dstl, kp, v0, v1)                                   \
        {                                                                     \
            uint32_t h0, l0, h1, l1, h2, l2, h3, l3;                          \
            split2((v0).x, (v1).x, h0, l0);                                   \
            split2((v0).y, (v1).y, h1, l1);                                   \
            split2((v0).z, (v1).z, h2, l2);                                   \
            split2((v0).w, (v1).w, h3, l3);                                   \
            *(uint4*)&(dsth)[(kp) * BSTR + bcol] = make_uint4(h0, h1, h2, h3);\
            *(uint4*)&(dstl)[(kp) * BSTR + bcol] = make_uint4(l0, l1, l2, l3);\
        }

    fa00 = *(const float4*)(pA0);
    fa01 = *(const float4*)(pA0 + 4);
    fa10 = *(const float4*)(pA1);
    fa11 = *(const float4*)(pA1 + 4);
    fb00 = *(const float4*)(pB00);
    fb01 = *(const float4*)(pB01);
    fb10 = *(const float4*)(pB10);
    fb11 = *(const float4*)(pB11);

    STORE_A(sAh, sAl, arow, fa00, fa01);
    STORE_A(sAh, sAl, arow + 64, fa10, fa11);
    STORE_B(sBh, sBl, brow, fb00, fb01);
    STORE_B(sBh, sBl, brow + 8, fb10, fb11);
    __syncthreads();

    const int gr = lane >> 2;
    const int qc = lane & 3;

    for (int kt = 0; kt < NT; kt++) {
        if (kt + 1 < NT) {
            int ko = (kt + 1) * GBK;
            fa00 = *(const float4*)(pA0 + ko);
            fa01 = *(const float4*)(pA0 + ko + 4);
            fa10 = *(const float4*)(pA1 + ko);
            fa11 = *(const float4*)(pA1 + ko + 4);
            fb00 = *(const float4*)(pB00 + (size_t)ko * N);
            fb01 = *(const float4*)(pB01 + (size_t)ko * N);
            fb10 = *(const float4*)(pB10 + (size_t)ko * N);
            fb11 = *(const float4*)(pB11 + (size_t)ko * N);
        }

        const uint32_t* Ah = sAh + (kt & 1) * A_STAGE;
        const uint32_t* Al = sAl + (kt & 1) * A_STAGE;
        const uint32_t* Bh = sBh + (kt & 1) * B_STAGE;
        const uint32_t* Bl = sBl + (kt & 1) * B_STAGE;

        #pragma unroll
        for (int ks = 0; ks < 2; ks++) {
            const int kp0 = ks * 8 + qc;
            uint32_t ah[4][4], al[4][4], bh[4][2], bl[4][2];
            #pragma unroll
            for (int mt = 0; mt < 4; mt++) {
                const int m = m_base + mt * 16 + gr;
                ah[mt][0] = Ah[m * ASTR + kp0];
                ah[mt][1] = Ah[(m + 8) * ASTR + kp0];
                ah[mt][2] = Ah[m * ASTR + kp0 + 4];
                ah[mt][3] = Ah[(m + 8) * ASTR + kp0 + 4];
                al[mt][0] = Al[m * ASTR + kp0];
                al[mt][1] = Al[(m + 8) * ASTR + kp0];
                al[mt][2] = Al[m * ASTR + kp0 + 4];
                al[mt][3] = Al[(m + 8) * ASTR + kp0 + 4];
            }
            #pragma unroll
            for (int nt = 0; nt < 4; nt++) {
                const int n = n_base + nt * 8 + gr;
                bh[nt][0] = Bh[kp0 * BSTR + n];
                bh[nt][1] = Bh[(kp0 + 4) * BSTR + n];
                bl[nt][0] = Bl[kp0 * BSTR + n];
                bl[nt][1] = Bl[(kp0 + 4) * BSTR + n];
            }
            #pragma unroll
            for (int mt = 0; mt < 4; mt++)
                #pragma unroll
                for (int nt = 0; nt < 4; nt++) {
                    mma_bf16(acc[mt][nt], ah[mt], bh[nt]);
                    mma_bf16(acc[mt][nt], ah[mt], bl[nt]);
                    mma_bf16(acc[mt][nt], al[mt], bh[nt]);
                }
        }

        if (kt + 1 < NT) {
            uint32_t* dAh = sAh + ((kt + 1) & 1) * A_STAGE;
            uint32_t* dAl = sAl + ((kt + 1) & 1) * A_STAGE;
            uint32_t* dBh = sBh + ((kt + 1) & 1) * B_STAGE;
            uint32_t* dBl = sBl + ((kt + 1) & 1) * B_STAGE;
            STORE_A(dAh, dAl, arow, fa00, fa01);
            STORE_A(dAh, dAl, arow + 64, fa10, fa11);
            STORE_B(dBh, dBl, brow, fb00, fb01);
            STORE_B(dBh, dBl, brow + 8, fb10, fb11);
        }
        __syncthreads();
    }
    #undef STORE_A
    #undef STORE_B

    #pragma unroll
    for (int mt = 0; mt < 4; mt++) {
        #pragma unroll
        for (int nt = 0; nt < 4; nt++) {
            int r = row0 + m_base + mt * 16 + gr;
            int c = col0 + n_base + nt * 8 + 2 * qc;
            *(float2*)&C[(size_t)r * N + c] =
                make_float2(acc[mt][nt][0], acc[mt][nt][1]);
            *(float2*)&C[(size_t)(r + 8) * N + c] =
                make_float2(acc[mt][nt][2], acc[mt][nt][3]);
        }
    }
}

// ---------------------------------------------------------------------------
// Tensor-core windowed flash attention, bf16 hi/lo split, ldmatrix fragments.
// CTA = (b, h, 64-query tile), 256 threads (8 warps: QK 4x2, PV 4x2).
// Keys in 6 chunks of 96 (window span 576 = 6x96). Small smem (~98KB) so
// TWO CTAs co-reside per SM and their phases overlap.
// Layouts (u32 words; odd quad strides => LDSM conflict-free):
//   sQ [q=64][kp]      stride 36
//   sK [key=96][kp]    stride 36
//   sV [d=64][keypair] stride 52  (V transposed, 48 kp)
//   sP [q=64][keypair] stride 52  (48 kp)
// ---------------------------------------------------------------------------
constexpr int AQT = 64;
constexpr int AKT = 96;
constexpr int NCHUNK = 6;
constexpr int QSTR2 = 36;
constexpr int KSTR2 = 36;
constexpr int VSTR2 = 52;
constexpr int PSTR2 = 52;
constexpr int ATHREADS = 256;

constexpr int OFF_QH = 0;
constexpr int OFF_QL = OFF_QH + AQT * QSTR2;        // 2304
constexpr int OFF_KH = OFF_QL + AQT * QSTR2;        // 4608
constexpr int OFF_KL = OFF_KH + AKT * KSTR2;        // 8064
constexpr int OFF_VH = OFF_KL + AKT * KSTR2;        // 11520
constexpr int OFF_VL = OFF_VH + 64 * VSTR2;         // 14848
constexpr int OFF_PH = OFF_VL + 64 * VSTR2;         // 18176
constexpr int OFF_PL = OFF_PH + AQT * PSTR2;        // 21504
constexpr int OFF_RED = OFF_PL + AQT * PSTR2;       // 24832 (float[64*2])
constexpr int OFF_M  = OFF_RED + 128;
constexpr int OFF_L  = OFF_M + 64;
constexpr int OFF_F  = OFF_L + 64;
constexpr int ATTN_SMEM_WORDS = OFF_F + 64;         // 25152
constexpr int ATTN_SMEM_BYTES = ATTN_SMEM_WORDS * 4;  // 100608

__global__ __launch_bounds__(ATHREADS, 2) void attn_tc_kernel()
{
    extern __shared__ uint32_t sm[];
    uint32_t* sQh = sm + OFF_QH;
    uint32_t* sQl = sm + OFF_QL;
    uint32_t* sKh = sm + OFF_KH;
    uint32_t* sKl = sm + OFF_KL;
    uint32_t* sVh = sm + OFF_VH;
    uint32_t* sVl = sm + OFF_VL;
    uint32_t* sPh = sm + OFF_PH;
    uint32_t* sPl = sm + OFF_PL;
    float* red = (float*)(sm + OFF_RED);
    float* mS  = (float*)(sm + OFF_M);
    float* lS  = (float*)(sm + OFF_L);
    float* fS  = (float*)(sm + OFF_F);

    const int tid  = threadIdx.x;
    const int lane = tid & 31;
    const int wid  = tid >> 5;     // 0..7
    const int gr = lane >> 2;
    const int qc = lane & 3;
    const int wm = wid >> 1;       // 0..3
    const int wn = wid & 1;        // 0..1
    const int m0 = wm * 16;

    const int t0 = blockIdx.x * AQT;
    const int h  = blockIdx.y;
    const int b  = blockIdx.z;
    const float slope = exp2f(-(float)(h + 1));

    const float* Qb = g_q   + (size_t)b * S_LEN * EMB + h * DH;
    const float* Kb = g_k   + (size_t)b * S_LEN * EMB + h * DH;
    const float* Vb = g_v   + (size_t)b * S_LEN * EMB + h * DH;
    float*       Ob = g_att + (size_t)b * S_LEN * EMB + h * DH;

    // ldmatrix lane-address components
    const int lrow8  = (lane & 7);
    const int lmsel  = (lane >> 3) & 1;
    const int lhsel  = (lane >> 4) & 1;

    // A-frag (Q / P)
    const uint32_t qh_base = smem_u32(sQh) +
        (((m0 + lrow8 + lmsel * 8) * QSTR2) + lhsel * 4) * 4;
    const uint32_t ql_base = qh_base + (OFF_QL - OFF_QH) * 4;
    const uint32_t ph_base = smem_u32(sPh) +
        (((m0 + lrow8 + lmsel * 8) * PSTR2) + lhsel * 4) * 4;
    const uint32_t pl_base = ph_base + (OFF_PL - OFF_PH) * 4;
    // B-frag (K): warp covers keys [wn*48, wn*48+48)
    const int nbase = wn * 48;
    const uint32_t kh_base = smem_u32(sKh) +
        (((nbase + lrow8 + lhsel * 8) * KSTR2) + lmsel * 4) * 4;
    const uint32_t kl_base = kh_base + (OFF_KL - OFF_KH) * 4;
    // B-frag (V): warp covers dims [wn*32, wn*32+32)
    const int nb2 = wn * 32;
    const uint32_t vh_base = smem_u32(sVh) +
        (((nb2 + lrow8 + lhsel * 8) * VSTR2) + lmsel * 4) * 4;
    const uint32_t vl_base = vh_base + (OFF_VL - OFF_VH) * 4;

    // Load Q tile: row q holds kp 0..31
    for (int idx = tid; idx < AQT * 16; idx += ATHREADS) {
        int q = idx >> 4;
        int dg = idx & 15;
        float4 v = *(const float4*)&Qb[(size_t)(t0 + q) * EMB + dg * 4];
        uint32_t h0, l0, h1, l1;
        split2(v.x, v.y, h0, l0);
        split2(v.z, v.w, h1, l1);
        int o = q * QSTR2 + 2 * dg;
        sQh[o] = h0; sQh[o + 1] = h1;
        sQl[o] = l0; sQl[o + 1] = l1;
    }
    if (tid < AQT) { mS[tid] = -1e30f; lS[tid] = 0.0f; }

    float o[4][4] = {};

    const int base = t0 - HALF;

    #pragma unroll 1
    for (int c = 0; c < NCHUNK; c++) {
        const int cs = base + c * AKT;
        if (cs + AKT <= 0 || cs >= S_LEN) continue;

        // ---- load K chunk: row key holds kp 0..31 ----
        for (int idx = tid; idx < AKT * 16; idx += ATHREADS) {
            int key = idx >> 4;
            int dg = idx & 15;
            int T = cs + key;
            float4 kv = make_float4(0.f, 0.f, 0.f, 0.f);
            if (T >= 0 && T < S_LEN)
                kv = *(const float4*)&Kb[(size_t)T * EMB + dg * 4];
            uint32_t h0, l0, h1, l1;
            split2(kv.x, kv.y, h0, l0);
            split2(kv.z, kv.w, h1, l1);
            int oo = key * KSTR2 + 2 * dg;
            sKh[oo] = h0; sKh[oo + 1] = h1;
            sKl[oo] = l0; sKl[oo + 1] = l1;
        }
        // ---- load V transposed: row d holds keypairs 0..47 ----
        for (int idx = tid; idx < 48 * 16; idx += ATHREADS) {
            int kp = idx >> 4;
            int dg = idx & 15;
            int d = dg * 4;
            int T0 = cs + 2 * kp, T1 = T0 + 1;
            float4 v0 = make_float4(0.f, 0.f, 0.f, 0.f);
            float4 v1 = make_float4(0.f, 0.f, 0.f, 0.f);
            if (T0 >= 0 && T0 < S_LEN) v0 = *(const float4*)&Vb[(size_t)T0 * EMB + d];
            if (T1 >= 0 && T1 < S_LEN) v1 = *(const float4*)&Vb[(size_t)T1 * EMB + d];
            uint32_t hp, lp;
            split2(v0.x, v1.x, hp, lp); sVh[(d + 0) * VSTR2 + kp] = hp; sVl[(d + 0) * VSTR2 + kp] = lp;
            split2(v0.y, v1.y, hp, lp); sVh[(d + 1) * VSTR2 + kp] = hp; sVl[(d + 1) * VSTR2 + kp] = lp;
            split2(v0.z, v1.z, hp, lp); sVh[(d + 2) * VSTR2 + kp] = hp; sVl[(d + 2) * VSTR2 + kp] = lp;
            split2(v0.w, v1.w, hp, lp); sVh[(d + 3) * VSTR2 + kp] = hp; sVl[(d + 3) * VSTR2 + kp] = lp;
        }
        __syncthreads();

        // ---- S = Q @ K^T : warp tile 16 x 48 ----
        float s[6][4];
        #pragma unroll
        for (int nt = 0; nt < 6; nt++)
            #pragma unroll
            for (int i = 0; i < 4; i++) s[nt][i] = 0.f;

        #pragma unroll
        for (int ks = 0; ks < 4; ks++) {
            uint32_t ah[4], al[4];
            ldsm_x4(ah, qh_base + ks * 32);
            ldsm_x4(al, ql_base + ks * 32);
            #pragma unroll
            for (int ntp = 0; ntp < 3; ntp++) {
                uint32_t bh[4], bl[4];
                ldsm_x4(bh, kh_base + ks * 32 + ntp * (16 * KSTR2 * 4));
                ldsm_x4(bl, kl_base + ks * 32 + ntp * (16 * KSTR2 * 4));
                mma_bf16(s[2 * ntp],     ah, bh);
                mma_bf16(s[2 * ntp],     ah, bl);
                mma_bf16(s[2 * ntp],     al, bh);
                mma_bf16(s[2 * ntp + 1], ah, bh + 2);
                mma_bf16(s[2 * ntp + 1], ah, bl + 2);
                mma_bf16(s[2 * ntp + 1], al, bh + 2);
            }
        }

        // ---- scale + ALiBi + window mask; per-row max ----
        const int trow0 = t0 + m0 + gr;
        const int trow1 = trow0 + 8;
        float mx0 = -1e30f, mx1 = -1e30f;
        #pragma unroll
        for (int nt = 0; nt < 6; nt++) {
            int T0 = cs + nbase + nt * 8 + 2 * qc;
            int T1 = T0 + 1;
            bool in0 = (T0 >= 0) && (T0 < S_LEN);
            bool in1 = (T1 >= 0) && (T1 < S_LEN);
            int a00 = abs(trow0 - T0), a01 = abs(trow0 - T1);
            int a10 = abs(trow1 - T0), a11 = abs(trow1 - T1);
            s[nt][0] = (in0 && a00 <= HALF) ? fmaf(s[nt][0], 0.125f, -slope * (float)a00) : -1e30f;
            s[nt][1] = (in1 && a01 <= HALF) ? fmaf(s[nt][1], 0.125f, -slope * (float)a01) : -1e30f;
            s[nt][2] = (in0 && a10 <= HALF) ? fmaf(s[nt][2], 0.125f, -slope * (float)a10) : -1e30f;
            s[nt][3] = (in1 && a11 <= HALF) ? fmaf(s[nt][3], 0.125f, -slope * (float)a11) : -1e30f;
            mx0 = fmaxf(mx0, fmaxf(s[nt][0], s[nt][1]));
            mx1 = fmaxf(mx1, fmaxf(s[nt][2], s[nt][3]));
        }
        mx0 = fmaxf(mx0, __shfl_xor_sync(0xffffffffu, mx0, 1));
        mx0 = fmaxf(mx0, __shfl_xor_sync(0xffffffffu, mx0, 2));
        mx1 = fmaxf(mx1, __shfl_xor_sync(0xffffffffu, mx1, 1));
        mx1 = fmaxf(mx1, __shfl_xor_sync(0xffffffffu, mx1, 2));
        if (qc == 0) {
            red[(m0 + gr) * 2 + wn] = mx0;
            red[(m0 + gr + 8) * 2 + wn] = mx1;
        }
        __syncthreads();

        if (tid < AQT) {
            float cm = fmaxf(red[tid * 2], red[tid * 2 + 1]);
            float mold = mS[tid];
            float mnew = fmaxf(mold, cm);
            fS[tid] = __expf(mold - mnew);
            mS[tid] = mnew;
        }
        __syncthreads();

        // ---- exp, stage P [q][kp], partial sums, rescale O ----
        const float mrow0 = mS[m0 + gr];
        const float mrow1 = mS[m0 + gr + 8];
        float sum0 = 0.f, sum1 = 0.f;
        #pragma unroll
        for (int nt = 0; nt < 6; nt++) {
            float p00 = (s[nt][0] > -5e29f) ? __expf(s[nt][0] - mrow0) : 0.f;
            float p01 = (s[nt][1] > -5e29f) ? __expf(s[nt][1] - mrow0) : 0.f;
            float p10 = (s[nt][2] > -5e29f) ? __expf(s[nt][2] - mrow1) : 0.f;
            float p11 = (s[nt][3] > -5e29f) ? __expf(s[nt][3] - mrow1) : 0.f;
            sum0 += p00 + p01;
            sum1 += p10 + p11;
            int kp = wn * 24 + nt * 4 + qc;
            uint32_t hp, lp;
            split2(p00, p01, hp, lp);
            sPh[(m0 + gr) * PSTR2 + kp] = hp;
            sPl[(m0 + gr) * PSTR2 + kp] = lp;
            split2(p10, p11, hp, lp);
            sPh[(m0 + gr + 8) * PSTR2 + kp] = hp;
            sPl[(m0 + gr + 8) * PSTR2 + kp] = lp;
        }
        sum0 += __shfl_xor_sync(0xffffffffu, sum0, 1);
        sum0 += __shfl_xor_sync(0xffffffffu, sum0, 2);
        sum1 += __shfl_xor_sync(0xffffffffu, sum1, 1);
        sum1 += __shfl_xor_sync(0xffffffffu, sum1, 2);
        if (qc == 0) {
            red[(m0 + gr) * 2 + wn] = sum0;
            red[(m0 + gr + 8) * 2 + wn] = sum1;
        }
        const float f0 = fS[m0 + gr];
        const float f1 = fS[m0 + gr + 8];
        #pragma unroll
        for (int nt = 0; nt < 4; nt++) {
            o[nt][0] *= f0; o[nt][1] *= f0;
            o[nt][2] *= f1; o[nt][3] *= f1;
        }
        __syncthreads();

        if (tid < AQT)
            lS[tid] = lS[tid] * fS[tid] + red[tid * 2] + red[tid * 2 + 1];

        // ---- O += P @ V : warp tile 16 x 32, 6 k-steps ----
        #pragma unroll
        for (int ks = 0; ks < 6; ks++) {
            uint32_t ah[4], al[4];
            ldsm_x4(ah, ph_base + ks * 32);
            ldsm_x4(al, pl_base + ks * 32);
            #pragma unroll
            for (int ntp = 0; ntp < 2; ntp++) {
                uint32_t bh[4], bl[4];
                ldsm_x4(bh, vh_base + ks * 32 + ntp * (16 * VSTR2 * 4));
                ldsm_x4(bl, vl_base + ks * 32 + ntp * (16 * VSTR2 * 4));
                mma_bf16(o[2 * ntp],     ah, bh);
                mma_bf16(o[2 * ntp],     ah, bl);
                mma_bf16(o[2 * ntp],     al, bh);
                mma_bf16(o[2 * ntp + 1], ah, bh + 2);
                mma_bf16(o[2 * ntp + 1], ah, bl + 2);
                mma_bf16(o[2 * ntp + 1], al, bh + 2);
            }
        }
        __syncthreads();
    }

    // ---- normalize and write ----
    const int trow0 = t0 + m0 + gr;
    const float inv0 = 1.0f / lS[m0 + gr];
    const float inv1 = 1.0f / lS[m0 + gr + 8];
    #pragma unroll
    for (int nt = 0; nt < 4; nt++) {
        int d = nb2 + nt * 8 + 2 * qc;
        *(float2*)&Ob[(size_t)trow0 * EMB + d] =
            make_float2(o[nt][0] * inv0, o[nt][1] * inv0);
        *(float2*)&Ob[(size_t)(trow0 + 8) * EMB + d] =
            make_float2(o[nt][2] * inv1, o[nt][3] * inv1);
    }
}

// ---------------------------------------------------------------------------
extern "C" void kernel_launch(void* const* d_in, const int* in_sizes, int n_in,
                              void* d_out, int out_size)
{
    (void)in_sizes; (void)n_in; (void)out_size;
    const float* inputs_q  = (const float*)d_in[0];
    const float* inputs_kv = (const float*)d_in[1];
    const float* w_q = (const float*)d_in[2];
    const float* w_k = (const float*)d_in[3];
    const float* w_v = (const float*)d_in[4];
    const float* w_o = (const float*)d_in[5];
    float* out = (float*)d_out;

    float *qb, *kb, *vb, *ab;
    cudaGetSymbolAddress((void**)&qb, g_q);
    cudaGetSymbolAddress((void**)&kb, g_k);
    cudaGetSymbolAddress((void**)&vb, g_v);
    cudaGetSymbolAddress((void**)&ab, g_att);

    cudaFuncSetAttribute(gemm_bf16_kernel,
                         cudaFuncAttributeMaxDynamicSharedMemorySize,
                         GEMM_SMEM_BYTES);
    cudaFuncSetAttribute(attn_tc_kernel,
                         cudaFuncAttributeMaxDynamicSharedMemorySize,
                         ATTN_SMEM_BYTES);

    dim3 gGemm(EMB / GBN, ROWS / GBM);   // (4, 64)
    gemm_bf16_kernel<<<gGemm, 256, GEMM_SMEM_BYTES>>>(inputs_q,  w_q, qb, ROWS, EMB, EMB);
    gemm_bf16_kernel<<<gGemm, 256, GEMM_SMEM_BYTES>>>(inputs_kv, w_k, kb, ROWS, EMB, EMB);
    gemm_bf16_kernel<<<gGemm, 256, GEMM_SMEM_BYTES>>>(inputs_kv, w_v, vb, ROWS, EMB, EMB);

    dim3 gAttn(S_LEN / AQT, NH, BATCH);  // (64, 8, 2)
    attn_tc_kernel<<<gAttn, ATHREADS, ATTN_SMEM_BYTES>>>();

    gemm_bf16_kernel<<<gGemm, 256, GEMM_SMEM_BYTES>>>(ab, w_o, out, ROWS, EMB, EMB);
}

// round 11
// speedup vs baseline: 1.0705x; 1.0211x over previous
#include <cuda_runtime.h>
#include <math.h>
#include <stdint.h>

// Problem constants
constexpr int S_LEN = 4096;
constexpr int BATCH = 2;
constexpr int EMB   = 512;   // E and also H*D
constexpr int NH    = 8;
constexpr int DH    = 64;
constexpr int HALF  = 256;   // sliding window half-width
constexpr int ROWS  = BATCH * S_LEN;  // 8192
constexpr int KPR   = EMB / 2;        // 256 kpairs per row

// Scratch (allocation-free rule: __device__ globals)
// Pre-split bf16x2 hi/lo planes for q/k/v: [row][kpair] u32, row stride 256.
__device__ uint32_t g_qh[(size_t)ROWS * KPR];
__device__ uint32_t g_ql[(size_t)ROWS * KPR];
__device__ uint32_t g_kh[(size_t)ROWS * KPR];
__device__ uint32_t g_kl[(size_t)ROWS * KPR];
__device__ uint32_t g_vh[(size_t)ROWS * KPR];
__device__ uint32_t g_vl[(size_t)ROWS * KPR];
__device__ float    g_att[(size_t)ROWS * EMB];

// ---------------------------------------------------------------------------
// helpers
// ---------------------------------------------------------------------------
__device__ __forceinline__ void split2(float x0, float x1,
                                       uint32_t& hp, uint32_t& lp) {
    asm("cvt.rn.bf16x2.f32 %0, %1, %2;" : "=r"(hp) : "f"(x1), "f"(x0));
    float h0 = __uint_as_float(hp << 16);
    float h1 = __uint_as_float(hp & 0xffff0000u);
    float r0 = x0 - h0;
    float r1 = x1 - h1;
    asm("cvt.rn.bf16x2.f32 %0, %1, %2;" : "=r"(lp) : "f"(r1), "f"(r0));
}

__device__ __forceinline__ void mma_bf16(float d[4], const uint32_t a[4],
                                         const uint32_t b[2]) {
    asm volatile(
        "mma.sync.aligned.m16n8k16.row.col.f32.bf16.bf16.f32 "
        "{%0,%1,%2,%3}, {%4,%5,%6,%7}, {%8,%9}, {%0,%1,%2,%3};\n"
        : "+f"(d[0]), "+f"(d[1]), "+f"(d[2]), "+f"(d[3])
        : "r"(a[0]), "r"(a[1]), "r"(a[2]), "r"(a[3]), "r"(b[0]), "r"(b[1]));
}

__device__ __forceinline__ void ldsm_x4(uint32_t r[4], uint32_t addr) {
    asm volatile(
        "ldmatrix.sync.aligned.m8n8.x4.shared.b16 {%0,%1,%2,%3}, [%4];"
        : "=r"(r[0]), "=r"(r[1]), "=r"(r[2]), "=r"(r[3]) : "r"(addr));
}

__device__ __forceinline__ uint32_t smem_u32(const void* p) {
    return (uint32_t)__cvta_generic_to_shared(p);
}

__device__ __forceinline__ uint32_t prmt(uint32_t a, uint32_t b, uint32_t s) {
    uint32_t d;
    asm("prmt.b32 %0, %1, %2, %3;" : "=r"(d) : "r"(a), "r"(b), "r"(s));
    return d;
}

// ---------------------------------------------------------------------------
// Split-bf16 tensor-core GEMM (R4-validated core). C[M,N] = A[M,K] @ B[K,N].
// SPLIT_OUT=true: write hi/lo bf16x2 arrays (for attention consumption).
// SPLIT_OUT=false: write fp32 C.
// ---------------------------------------------------------------------------
constexpr int GBM = 128, GBN = 128, GBK = 32;
constexpr int KP  = GBK / 2;
constexpr int ASTR = 20;
constexpr int BSTR = 136;
constexpr int A_STAGE = GBM * ASTR;
constexpr int B_STAGE = KP * BSTR;
constexpr int GEMM_SMEM_BYTES = (4 * A_STAGE + 4 * B_STAGE) * 4;

template <bool SPLIT_OUT>
__global__ __launch_bounds__(256, 1) void gemm_bf16_kernel(
    const float* __restrict__ A, const float* __restrict__ B,
    float* __restrict__ C, uint32_t* __restrict__ Ch, uint32_t* __restrict__ Cl,
    int M, int N, int K)
{
    extern __shared__ uint32_t sm[];
    uint32_t* sAh = sm;
    uint32_t* sAl = sAh + 2 * A_STAGE;
    uint32_t* sBh = sAl + 2 * A_STAGE;
    uint32_t* sBl = sBh + 2 * B_STAGE;

    const int tid  = threadIdx.x;
    const int lane = tid & 31;
    const int wid  = tid >> 5;
    const int m_base = (wid >> 2) * 64;
    const int n_base = (wid & 3) * 32;
    const int row0 = blockIdx.y * GBM;
    const int col0 = blockIdx.x * GBN;

    const int arow  = tid >> 2;
    const int acolg = (tid & 3) * 8;
    const int akp   = (tid & 3) * 4;
    const int brow = tid >> 5;
    const int bcol = (tid & 31) * 4;

    const float* pA0 = A + (size_t)(row0 + arow) * K + acolg;
    const float* pA1 = A + (size_t)(row0 + arow + 64) * K + acolg;
    const float* pB00 = B + (size_t)(2 * brow) * N + col0 + bcol;
    const float* pB01 = B + (size_t)(2 * brow + 1) * N + col0 + bcol;
    const float* pB10 = B + (size_t)(2 * (brow + 8)) * N + col0 + bcol;
    const float* pB11 = B + (size_t)(2 * (brow + 8) + 1) * N + col0 + bcol;

    const int NT = K / GBK;

    float acc[4][4][4] = {};
    float4 fa00, fa01, fa10, fa11;
    float4 fb00, fb01, fb10, fb11;

    #define STORE_A(dsth, dstl, r, v0, v1)                                    \
        {                                                                     \
            uint32_t h0, l0, h1, l1, h2, l2, h3, l3;                          \
            split2((v0).x, (v0).y, h0, l0);                                   \
            split2((v0).z, (v0).w, h1, l1);                                   \
            split2((v1).x, (v1).y, h2, l2);                                   \
            split2((v1).z, (v1).w, h3, l3);                                   \
            *(uint4*)&(dsth)[(r) * ASTR + akp] = make_uint4(h0, h1, h2, h3);  \
            *(uint4*)&(dstl)[(r) * ASTR + akp] = make_uint4(l0, l1, l2, l3);  \
        }

    #define STORE_B(dsth, dstl, kp, v0, v1)                                   \
        {                                                                     \
            uint32_t h0, l0, h1, l1, h2, l2, h3, l3;                          \
            split2((v0).x, (v1).x, h0, l0);                                   \
            split2((v0).y, (v1).y, h1, l1);                                   \
            split2((v0).z, (v1).z, h2, l2);                                   \
            split2((v0).w, (v1).w, h3, l3);                                   \
            *(uint4*)&(dsth)[(kp) * BSTR + bcol] = make_uint4(h0, h1, h2, h3);\
            *(uint4*)&(dstl)[(kp) * BSTR + bcol] = make_uint4(l0, l1, l2, l3);\
        }

    fa00 = *(const float4*)(pA0);
    fa01 = *(const float4*)(pA0 + 4);
    fa10 = *(const float4*)(pA1);
    fa11 = *(const float4*)(pA1 + 4);
    fb00 = *(const float4*)(pB00);
    fb01 = *(const float4*)(pB01);
    fb10 = *(const float4*)(pB10);
    fb11 = *(const float4*)(pB11);

    STORE_A(sAh, sAl, arow, fa00, fa01);
    STORE_A(sAh, sAl, arow + 64, fa10, fa11);
    STORE_B(sBh, sBl, brow, fb00, fb01);
    STORE_B(sBh, sBl, brow + 8, fb10, fb11);
    __syncthreads();

    const int gr = lane >> 2;
    const int qc = lane & 3;

    for (int kt = 0; kt < NT; kt++) {
        if (kt + 1 < NT) {
            int ko = (kt + 1) * GBK;
            fa00 = *(const float4*)(pA0 + ko);
            fa01 = *(const float4*)(pA0 + ko + 4);
            fa10 = *(const float4*)(pA1 + ko);
            fa11 = *(const float4*)(pA1 + ko + 4);
            fb00 = *(const float4*)(pB00 + (size_t)ko * N);
            fb01 = *(const float4*)(pB01 + (size_t)ko * N);
            fb10 = *(const float4*)(pB10 + (size_t)ko * N);
            fb11 = *(const float4*)(pB11 + (size_t)ko * N);
        }

        const uint32_t* Ah = sAh + (kt & 1) * A_STAGE;
        const uint32_t* Al = sAl + (kt & 1) * A_STAGE;
        const uint32_t* Bh = sBh + (kt & 1) * B_STAGE;
        const uint32_t* Bl = sBl + (kt & 1) * B_STAGE;

        #pragma unroll
        for (int ks = 0; ks < 2; ks++) {
            const int kp0 = ks * 8 + qc;
            uint32_t ah[4][4], al[4][4], bh[4][2], bl[4][2];
            #pragma unroll
            for (int mt = 0; mt < 4; mt++) {
                const int m = m_base + mt * 16 + gr;
                ah[mt][0] = Ah[m * ASTR + kp0];
                ah[mt][1] = Ah[(m + 8) * ASTR + kp0];
                ah[mt][2] = Ah[m * ASTR + kp0 + 4];
                ah[mt][3] = Ah[(m + 8) * ASTR + kp0 + 4];
                al[mt][0] = Al[m * ASTR + kp0];
                al[mt][1] = Al[(m + 8) * ASTR + kp0];
                al[mt][2] = Al[m * ASTR + kp0 + 4];
                al[mt][3] = Al[(m + 8) * ASTR + kp0 + 4];
            }
            #pragma unroll
            for (int nt = 0; nt < 4; nt++) {
                const int n = n_base + nt * 8 + gr;
                bh[nt][0] = Bh[kp0 * BSTR + n];
                bh[nt][1] = Bh[(kp0 + 4) * BSTR + n];
                bl[nt][0] = Bl[kp0 * BSTR + n];
                bl[nt][1] = Bl[(kp0 + 4) * BSTR + n];
            }
            #pragma unroll
            for (int mt = 0; mt < 4; mt++)
                #pragma unroll
                for (int nt = 0; nt < 4; nt++) {
                    mma_bf16(acc[mt][nt], ah[mt], bh[nt]);
                    mma_bf16(acc[mt][nt], ah[mt], bl[nt]);
                    mma_bf16(acc[mt][nt], al[mt], bh[nt]);
                }
        }

        if (kt + 1 < NT) {
            uint32_t* dAh = sAh + ((kt + 1) & 1) * A_STAGE;
            uint32_t* dAl = sAl + ((kt + 1) & 1) * A_STAGE;
            uint32_t* dBh = sBh + ((kt + 1) & 1) * B_STAGE;
            uint32_t* dBl = sBl + ((kt + 1) & 1) * B_STAGE;
            STORE_A(dAh, dAl, arow, fa00, fa01);
            STORE_A(dAh, dAl, arow + 64, fa10, fa11);
            STORE_B(dBh, dBl, brow, fb00, fb01);
            STORE_B(dBh, dBl, brow + 8, fb10, fb11);
        }
        __syncthreads();
    }
    #undef STORE_A
    #undef STORE_B

    #pragma unroll
    for (int mt = 0; mt < 4; mt++) {
        #pragma unroll
        for (int nt = 0; nt < 4; nt++) {
            int r = row0 + m_base + mt * 16 + gr;
            int c = col0 + n_base + nt * 8 + 2 * qc;
            if constexpr (SPLIT_OUT) {
                int kp = c >> 1;
                uint32_t hp, lp;
                split2(acc[mt][nt][0], acc[mt][nt][1], hp, lp);
                Ch[(size_t)r * KPR + kp] = hp;
                Cl[(size_t)r * KPR + kp] = lp;
                split2(acc[mt][nt][2], acc[mt][nt][3], hp, lp);
                Ch[(size_t)(r + 8) * KPR + kp] = hp;
                Cl[(size_t)(r + 8) * KPR + kp] = lp;
            } else {
                *(float2*)&C[(size_t)r * N + c] =
                    make_float2(acc[mt][nt][0], acc[mt][nt][1]);
                *(float2*)&C[(size_t)(r + 8) * N + c] =
                    make_float2(acc[mt][nt][2], acc[mt][nt][3]);
            }
        }
    }
}

// ---------------------------------------------------------------------------
// Tensor-core windowed flash attention, split-bf16, ldmatrix fragments,
// PRE-SPLIT inputs (pure-copy loads) and FIXED-MAX softmax (no running max,
// no rescale; row sums accumulate in registers; 3 barriers/chunk).
// CTA = (b, h, 64-query tile), 256 threads, 6 chunks of 96 keys, 2 CTAs/SM.
// ---------------------------------------------------------------------------
constexpr int AQT = 64;
constexpr int AKT = 96;
constexpr int NCHUNK = 6;
constexpr int QSTR2 = 36;
constexpr int KSTR2 = 36;
constexpr int VSTR2 = 52;
constexpr int PSTR2 = 52;
constexpr int ATHREADS = 256;
constexpr float FIXM = 12.0f;   // fixed softmax shift (scores bounded << 12+80)

constexpr int OFF_QH = 0;
constexpr int OFF_QL = OFF_QH + AQT * QSTR2;        // 2304
constexpr int OFF_KH = OFF_QL + AQT * QSTR2;        // 4608
constexpr int OFF_KL = OFF_KH + AKT * KSTR2;        // 8064
constexpr int OFF_VH = OFF_KL + AKT * KSTR2;        // 11520
constexpr int OFF_VL = OFF_VH + 64 * VSTR2;         // 14848
constexpr int OFF_PH = OFF_VL + 64 * VSTR2;         // 18176
constexpr int OFF_PL = OFF_PH + AQT * PSTR2;        // 21504
constexpr int OFF_RED = OFF_PL + AQT * PSTR2;       // 24832 (float[64*2])
constexpr int ATTN_SMEM_WORDS = OFF_RED + 128;      // 24960
constexpr int ATTN_SMEM_BYTES = ATTN_SMEM_WORDS * 4;  // 99840

__global__ __launch_bounds__(ATHREADS, 2) void attn_tc_kernel()
{
    extern __shared__ uint32_t sm[];
    uint32_t* sQh = sm + OFF_QH;
    uint32_t* sQl = sm + OFF_QL;
    uint32_t* sKh = sm + OFF_KH;
    uint32_t* sKl = sm + OFF_KL;
    uint32_t* sVh = sm + OFF_VH;
    uint32_t* sVl = sm + OFF_VL;
    uint32_t* sPh = sm + OFF_PH;
    uint32_t* sPl = sm + OFF_PL;
    float* red = (float*)(sm + OFF_RED);

    const int tid  = threadIdx.x;
    const int lane = tid & 31;
    const int wid  = tid >> 5;     // 0..7
    const int gr = lane >> 2;
    const int qc = lane & 3;
    const int wm = wid >> 1;       // 0..3
    const int wn = wid & 1;        // 0..1
    const int m0 = wm * 16;

    const int t0 = blockIdx.x * AQT;
    const int h  = blockIdx.y;
    const int b  = blockIdx.z;
    const float slope = exp2f(-(float)(h + 1));

    // pre-split plane pointers (row stride KPR u32, head col offset h*32)
    const uint32_t* Qh_p = g_qh + ((size_t)(b * S_LEN + t0)) * KPR + h * 32;
    const uint32_t* Ql_p = g_ql + ((size_t)(b * S_LEN + t0)) * KPR + h * 32;
    const uint32_t* Kh_p = g_kh + ((size_t)b * S_LEN) * KPR + h * 32;
    const uint32_t* Kl_p = g_kl + ((size_t)b * S_LEN) * KPR + h * 32;
    const uint32_t* Vh_p = g_vh + ((size_t)b * S_LEN) * KPR + h * 32;
    const uint32_t* Vl_p = g_vl + ((size_t)b * S_LEN) * KPR + h * 32;
    float* Ob = g_att + (size_t)b * S_LEN * EMB + h * DH;

    // ldmatrix lane-address components
    const int lrow8  = (lane & 7);
    const int lmsel  = (lane >> 3) & 1;
    const int lhsel  = (lane >> 4) & 1;

    const uint32_t qh_base = smem_u32(sQh) +
        (((m0 + lrow8 + lmsel * 8) * QSTR2) + lhsel * 4) * 4;
    const uint32_t ql_base = qh_base + (OFF_QL - OFF_QH) * 4;
    const uint32_t ph_base = smem_u32(sPh) +
        (((m0 + lrow8 + lmsel * 8) * PSTR2) + lhsel * 4) * 4;
    const uint32_t pl_base = ph_base + (OFF_PL - OFF_PH) * 4;
    const int nbase = wn * 48;
    const uint32_t kh_base = smem_u32(sKh) +
        (((nbase + lrow8 + lhsel * 8) * KSTR2) + lmsel * 4) * 4;
    const uint32_t kl_base = kh_base + (OFF_KL - OFF_KH) * 4;
    const int nb2 = wn * 32;
    const uint32_t vh_base = smem_u32(sVh) +
        (((nb2 + lrow8 + lhsel * 8) * VSTR2) + lmsel * 4) * 4;
    const uint32_t vl_base = vh_base + (OFF_VL - OFF_VH) * 4;

    // Load Q tile: pure copy of pre-split data (64 rows x 8 uint4)
    for (int idx = tid; idx < 512; idx += ATHREADS) {
        int q = idx >> 3;
        int j = idx & 7;
        uint4 vh = *(const uint4*)&Qh_p[(size_t)q * KPR + j * 4];
        uint4 vl = *(const uint4*)&Ql_p[(size_t)q * KPR + j * 4];
        *(uint4*)&sQh[q * QSTR2 + j * 4] = vh;
        *(uint4*)&sQl[q * QSTR2 + j * 4] = vl;
    }

    float o[4][4] = {};
    float sum0 = 0.f, sum1 = 0.f;   // fixed-max row-sum accumulators

    const int base = t0 - HALF;

    #pragma unroll 1
    for (int c = 0; c < NCHUNK; c++) {
        const int cs = base + c * AKT;
        if (cs + AKT <= 0 || cs >= S_LEN) continue;

        // ---- K chunk: pure copy (96 rows x 8 uint4) ----
        for (int idx = tid; idx < 768; idx += ATHREADS) {
            int key = idx >> 3;
            int j = idx & 7;
            int T = cs + key;
            uint4 vh = make_uint4(0, 0, 0, 0);
            uint4 vl = make_uint4(0, 0, 0, 0);
            if (T >= 0 && T < S_LEN) {
                vh = *(const uint4*)&Kh_p[(size_t)T * KPR + j * 4];
                vl = *(const uint4*)&Kl_p[(size_t)T * KPR + j * 4];
            }
            *(uint4*)&sKh[key * KSTR2 + j * 4] = vh;
            *(uint4*)&sKl[key * KSTR2 + j * 4] = vl;
        }
        // ---- V chunk: load 2 rows, repack (T0,T1) pairs via PRMT ----
        for (int idx = tid; idx < 384; idx += ATHREADS) {
            int kp = idx >> 3;    // 0..47
            int j = idx & 7;      // d group: d = 8j..8j+7
            int T0 = cs + 2 * kp, T1 = T0 + 1;
            uint4 ah = make_uint4(0, 0, 0, 0), al = make_uint4(0, 0, 0, 0);
            uint4 bh = make_uint4(0, 0, 0, 0), bl = make_uint4(0, 0, 0, 0);
            if (T0 >= 0 && T0 < S_LEN) {
                ah = *(const uint4*)&Vh_p[(size_t)T0 * KPR + j * 4];
                al = *(const uint4*)&Vl_p[(size_t)T0 * KPR + j * 4];
            }
            if (T1 >= 0 && T1 < S_LEN) {
                bh = *(const uint4*)&Vh_p[(size_t)T1 * KPR + j * 4];
                bl = *(const uint4*)&Vl_p[(size_t)T1 * KPR + j * 4];
            }
            int d0 = 8 * j;
            sVh[(d0 + 0) * VSTR2 + kp] = prmt(ah.x, bh.x, 0x5410);
            sVh[(d0 + 1) * VSTR2 + kp] = prmt(ah.x, bh.x, 0x7632);
            sVh[(d0 + 2) * VSTR2 + kp] = prmt(ah.y, bh.y, 0x5410);
            sVh[(d0 + 3) * VSTR2 + kp] = prmt(ah.y, bh.y, 0x7632);
            sVh[(d0 + 4) * VSTR2 + kp] = prmt(ah.z, bh.z, 0x5410);
            sVh[(d0 + 5) * VSTR2 + kp] = prmt(ah.z, bh.z, 0x7632);
            sVh[(d0 + 6) * VSTR2 + kp] = prmt(ah.w, bh.w, 0x5410);
            sVh[(d0 + 7) * VSTR2 + kp] = prmt(ah.w, bh.w, 0x7632);
            sVl[(d0 + 0) * VSTR2 + kp] = prmt(al.x, bl.x, 0x5410);
            sVl[(d0 + 1) * VSTR2 + kp] = prmt(al.x, bl.x, 0x7632);
            sVl[(d0 + 2) * VSTR2 + kp] = prmt(al.y, bl.y, 0x5410);
            sVl[(d0 + 3) * VSTR2 + kp] = prmt(al.y, bl.y, 0x7632);
            sVl[(d0 + 4) * VSTR2 + kp] = prmt(al.z, bl.z, 0x5410);
            sVl[(d0 + 5) * VSTR2 + kp] = prmt(al.z, bl.z, 0x7632);
            sVl[(d0 + 6) * VSTR2 + kp] = prmt(al.w, bl.w, 0x5410);
            sVl[(d0 + 7) * VSTR2 + kp] = prmt(al.w, bl.w, 0x7632);
        }
        __syncthreads();

        // ---- S = Q @ K^T : warp tile 16 x 48 ----
        float s[6][4];
        #pragma unroll
        for (int nt = 0; nt < 6; nt++)
            #pragma unroll
            for (int i = 0; i < 4; i++) s[nt][i] = 0.f;

        #pragma unroll
        for (int ks = 0; ks < 4; ks++) {
            uint32_t ah[4], al[4];
            ldsm_x4(ah, qh_base + ks * 32);
            ldsm_x4(al, ql_base + ks * 32);
            #pragma unroll
            for (int ntp = 0; ntp < 3; ntp++) {
                uint32_t bh[4], bl[4];
                ldsm_x4(bh, kh_base + ks * 32 + ntp * (16 * KSTR2 * 4));
                ldsm_x4(bl, kl_base + ks * 32 + ntp * (16 * KSTR2 * 4));
                mma_bf16(s[2 * ntp],     ah, bh);
                mma_bf16(s[2 * ntp],     ah, bl);
                mma_bf16(s[2 * ntp],     al, bh);
                mma_bf16(s[2 * ntp + 1], ah, bh + 2);
                mma_bf16(s[2 * ntp + 1], ah, bl + 2);
                mma_bf16(s[2 * ntp + 1], al, bh + 2);
            }
        }

        // ---- fixed-max softmax: p = exp(s*0.125 - slope*|dlt| - FIXM) ----
        const int trow0 = t0 + m0 + gr;
        const int trow1 = trow0 + 8;
        #pragma unroll
        for (int nt = 0; nt < 6; nt++) {
            int T0 = cs + nbase + nt * 8 + 2 * qc;
            int T1 = T0 + 1;
            bool in0 = (T0 >= 0) && (T0 < S_LEN);
            bool in1 = (T1 >= 0) && (T1 < S_LEN);
            int a00 = abs(trow0 - T0), a01 = abs(trow0 - T1);
            int a10 = abs(trow1 - T0), a11 = abs(trow1 - T1);
            float p00 = (in0 && a00 <= HALF)
                ? __expf(fmaf(s[nt][0], 0.125f, fmaf(-slope, (float)a00, -FIXM))) : 0.f;
            float p01 = (in1 && a01 <= HALF)
                ? __expf(fmaf(s[nt][1], 0.125f, fmaf(-slope, (float)a01, -FIXM))) : 0.f;
            float p10 = (in0 && a10 <= HALF)
                ? __expf(fmaf(s[nt][2], 0.125f, fmaf(-slope, (float)a10, -FIXM))) : 0.f;
            float p11 = (in1 && a11 <= HALF)
                ? __expf(fmaf(s[nt][3], 0.125f, fmaf(-slope, (float)a11, -FIXM))) : 0.f;
            sum0 += p00 + p01;
            sum1 += p10 + p11;
            int kp = wn * 24 + nt * 4 + qc;
            uint32_t hp, lp;
            split2(p00, p01, hp, lp);
            sPh[(m0 + gr) * PSTR2 + kp] = hp;
            sPl[(m0 + gr) * PSTR2 + kp] = lp;
            split2(p10, p11, hp, lp);
            sPh[(m0 + gr + 8) * PSTR2 + kp] = hp;
            sPl[(m0 + gr + 8) * PSTR2 + kp] = lp;
        }
        __syncthreads();

        // ---- O += P @ V : warp tile 16 x 32, 6 k-steps ----
        #pragma unroll
        for (int ks = 0; ks < 6; ks++) {
            uint32_t ah[4], al[4];
            ldsm_x4(ah, ph_base + ks * 32);
            ldsm_x4(al, pl_base + ks * 32);
            #pragma unroll
            for (int ntp = 0; ntp < 2; ntp++) {
                uint32_t bh[4], bl[4];
                ldsm_x4(bh, vh_base + ks * 32 + ntp * (16 * VSTR2 * 4));
                ldsm_x4(bl, vl_base + ks * 32 + ntp * (16 * VSTR2 * 4));
                mma_bf16(o[2 * ntp],     ah, bh);
                mma_bf16(o[2 * ntp],     ah, bl);
                mma_bf16(o[2 * ntp],     al, bh);
                mma_bf16(o[2 * ntp + 1], ah, bh + 2);
                mma_bf16(o[2 * ntp + 1], ah, bl + 2);
                mma_bf16(o[2 * ntp + 1], al, bh + 2);
            }
        }
        __syncthreads();
    }

    // ---- final row-sum reduce (once) ----
    sum0 += __shfl_xor_sync(0xffffffffu, sum0, 1);
    sum0 += __shfl_xor_sync(0xffffffffu, sum0, 2);
    sum1 += __shfl_xor_sync(0xffffffffu, sum1, 1);
    sum1 += __shfl_xor_sync(0xffffffffu, sum1, 2);
    if (qc == 0) {
        red[(m0 + gr) * 2 + wn] = sum0;
        red[(m0 + gr + 8) * 2 + wn] = sum1;
    }
    __syncthreads();

    const int trow0 = t0 + m0 + gr;
    const float inv0 = 1.0f / (red[(m0 + gr) * 2] + red[(m0 + gr) * 2 + 1]);
    const float inv1 = 1.0f / (red[(m0 + gr + 8) * 2] + red[(m0 + gr + 8) * 2 + 1]);
    #pragma unroll
    for (int nt = 0; nt < 4; nt++) {
        int d = nb2 + nt * 8 + 2 * qc;
        *(float2*)&Ob[(size_t)trow0 * EMB + d] =
            make_float2(o[nt][0] * inv0, o[nt][1] * inv0);
        *(float2*)&Ob[(size_t)(trow0 + 8) * EMB + d] =
            make_float2(o[nt][2] * inv1, o[nt][3] * inv1);
    }
}

// ---------------------------------------------------------------------------
extern "C" void kernel_launch(void* const* d_in, const int* in_sizes, int n_in,
                              void* d_out, int out_size)
{
    (void)in_sizes; (void)n_in; (void)out_size;
    const float* inputs_q  = (const float*)d_in[0];
    const float* inputs_kv = (const float*)d_in[1];
    const float* w_q = (const float*)d_in[2];
    const float* w_k = (const float*)d_in[3];
    const float* w_v = (const float*)d_in[4];
    const float* w_o = (const float*)d_in[5];
    float* out = (float*)d_out;

    uint32_t *qh, *ql, *kh, *kl, *vh, *vl;
    float* ab;
    cudaGetSymbolAddress((void**)&qh, g_qh);
    cudaGetSymbolAddress((void**)&ql, g_ql);
    cudaGetSymbolAddress((void**)&kh, g_kh);
    cudaGetSymbolAddress((void**)&kl, g_kl);
    cudaGetSymbolAddress((void**)&vh, g_vh);
    cudaGetSymbolAddress((void**)&vl, g_vl);
    cudaGetSymbolAddress((void**)&ab, g_att);

    cudaFuncSetAttribute(gemm_bf16_kernel<true>,
                         cudaFuncAttributeMaxDynamicSharedMemorySize,
                         GEMM_SMEM_BYTES);
    cudaFuncSetAttribute(gemm_bf16_kernel<false>,
                         cudaFuncAttributeMaxDynamicSharedMemorySize,
                         GEMM_SMEM_BYTES);
    cudaFuncSetAttribute(attn_tc_kernel,
                         cudaFuncAttributeMaxDynamicSharedMemorySize,
                         ATTN_SMEM_BYTES);

    dim3 gGemm(EMB / GBN, ROWS / GBM);   // (4, 64)
    gemm_bf16_kernel<true><<<gGemm, 256, GEMM_SMEM_BYTES>>>(
        inputs_q,  w_q, nullptr, qh, ql, ROWS, EMB, EMB);
    gemm_bf16_kernel<true><<<gGemm, 256, GEMM_SMEM_BYTES>>>(
        inputs_kv, w_k, nullptr, kh, kl, ROWS, EMB, EMB);
    gemm_bf16_kernel<true><<<gGemm, 256, GEMM_SMEM_BYTES>>>(
        inputs_kv, w_v, nullptr, vh, vl, ROWS, EMB, EMB);

    dim3 gAttn(S_LEN / AQT, NH, BATCH);  // (64, 8, 2)
    attn_tc_kernel<<<gAttn, ATHREADS, ATTN_SMEM_BYTES>>>();

    gemm_bf16_kernel<false><<<gGemm, 256, GEMM_SMEM_BYTES>>>(
        ab, w_o, out, nullptr, nullptr, ROWS, EMB, EMB);
}